// round 2
// baseline (speedup 1.0000x reference)
#include <cuda_runtime.h>

#define BDIM 8
#define CDIM 64
#define NDIM 256
#define FDIM 128
#define EPS 1e-5f

// Scratch (allocation-free rule: __device__ globals)
__device__ unsigned char g_mask[BDIM * CDIM * NDIM];       // mask byte per (b,c,n)
__device__ float  g_psupp[BDIM * CDIM * 2 * FDIM];         // per-(bc,chunk) supp vec partial
__device__ float  g_ptot [BDIM * CDIM * 2 * FDIM];         // per-(bc,chunk) total vec partial
__device__ float  g_psq  [BDIM * CDIM * 2 * 2];            // per-(bc,chunk) [ssq_supp, ssq_tot]
__device__ float2 g_w[BDIM * CDIM];                        // softmax weights per (b,c)
__device__ float  g_S1[BDIM * CDIM];                       // BN partial sum
__device__ float  g_S2[BDIM * CDIM];                       // BN partial sumsq
__device__ float2 g_stat[CDIM];                            // (mean, rstd) per channel

__device__ __forceinline__ float warpsum(float v) {
#pragma unroll
    for (int o = 16; o; o >>= 1) v += __shfl_xor_sync(0xffffffffu, v, o);
    return v;
}

// ---------------------------------------------------------------------------
// Kernel 1: reduction pass. 2 CTAs per (b,c), each handling 128 rows.
// 8 lanes per row: lane's f-chunk = (lane&7)*16 .. +16. Groups g = lane>>3
// handle 4 consecutive rows per iteration.
// ---------------------------------------------------------------------------
__global__ void __launch_bounds__(256, 3) k1(const float* __restrict__ h,
                                             const float* __restrict__ op) {
    const int bc    = blockIdx.x >> 1;
    const int chunk = blockIdx.x & 1;
    const int c     = bc & (CDIM - 1);
    const int tid   = threadIdx.x;
    const int w     = tid >> 5;
    const int lane  = tid & 31;
    const int g     = lane >> 3;   // row group within warp (0..3)
    const int j     = lane & 7;    // f-chunk index (0..7)

    const float* hbase = h + (size_t)bc * NDIM * FDIM;

    // s_lo = dot(source, op_lo): full-warp reduce, once (L1/L2-hot source row)
    const float4* op4 = (const float4*)(op + c * 2 * FDIM);
    {
    }
    const float4 olo = op4[lane];
    const float4 s0  = ((const float4*)hbase)[lane];
    const float s_lo = warpsum(s0.x * olo.x + s0.y * olo.y + s0.z * olo.z + s0.w * olo.w);

    // op_hi chunk for this lane: op[c][128 + j*16 .. +16]
    float ohi[16];
    {
        const float4* p = (const float4*)(op + c * 2 * FDIM + FDIM + j * 16);
#pragma unroll
        for (int k = 0; k < 4; k++) {
            float4 t = p[k];
            ohi[k * 4 + 0] = t.x; ohi[k * 4 + 1] = t.y;
            ohi[k * 4 + 2] = t.z; ohi[k * 4 + 3] = t.w;
        }
    }

    float acc_s[16], acc_t[16];
#pragma unroll
    for (int k = 0; k < 16; k++) { acc_s[k] = 0.f; acc_t[k] = 0.f; }
    float ssq_s = 0.f, ssq_t = 0.f;

    __shared__ float s_supp[FDIM];
    __shared__ float s_tot[FDIM];
    __shared__ float s_sq[2];
    if (tid < FDIM) { s_supp[tid] = 0.f; s_tot[tid] = 0.f; }
    if (tid < 2) s_sq[tid] = 0.f;
    __syncthreads();

    // 4 iterations: rows n = chunk*128 + i*32 + w*4 + g
    for (int i = 0; i < 4; i++) {
        const int n = chunk * 128 + i * 32 + w * 4 + g;
        const float4* rp = (const float4*)(hbase + (size_t)n * FDIM + j * 16);
        float v[16];
#pragma unroll
        for (int k = 0; k < 4; k++) {
            float4 t = rp[k];
            v[k * 4 + 0] = t.x; v[k * 4 + 1] = t.y;
            v[k * 4 + 2] = t.z; v[k * 4 + 3] = t.w;
        }
        float dot = 0.f, sq = 0.f;
#pragma unroll
        for (int k = 0; k < 16; k++) {
            dot = fmaf(v[k], ohi[k], dot);
            sq  = fmaf(v[k], v[k], sq);
        }
        // reduce dot over the 8-lane group (xor 1,2,4 stays within group)
        dot += __shfl_xor_sync(0xffffffffu, dot, 1);
        dot += __shfl_xor_sync(0xffffffffu, dot, 2);
        dot += __shfl_xor_sync(0xffffffffu, dot, 4);
        const bool  m = (dot + s_lo) >= 0.f;
        const float p = m ? 1.f : 0.f;
#pragma unroll
        for (int k = 0; k < 16; k++) {
            acc_s[k] = fmaf(p, v[k], acc_s[k]);
            acc_t[k] += v[k];
        }
        ssq_t += sq;
        ssq_s = fmaf(p, sq, ssq_s);
        if (j == 0) g_mask[bc * NDIM + n] = m ? 1 : 0;
    }

    // Reduce accumulators across the 4 groups (xor 8, 16), land on lanes 0..7
#pragma unroll
    for (int k = 0; k < 16; k++) {
        acc_s[k] += __shfl_xor_sync(0xffffffffu, acc_s[k], 8);
        acc_s[k] += __shfl_xor_sync(0xffffffffu, acc_s[k], 16);
        acc_t[k] += __shfl_xor_sync(0xffffffffu, acc_t[k], 8);
        acc_t[k] += __shfl_xor_sync(0xffffffffu, acc_t[k], 16);
    }
    if (lane < 8) {
#pragma unroll
        for (int k = 0; k < 16; k++) {
            atomicAdd(&s_supp[lane * 16 + k], acc_s[k]);
            atomicAdd(&s_tot [lane * 16 + k], acc_t[k]);
        }
    }
    ssq_s = warpsum(ssq_s);
    ssq_t = warpsum(ssq_t);
    if (lane == 0) { atomicAdd(&s_sq[0], ssq_s); atomicAdd(&s_sq[1], ssq_t); }
    __syncthreads();

    if (tid < FDIM) {
        g_psupp[(size_t)blockIdx.x * FDIM + tid] = s_supp[tid];
        g_ptot [(size_t)blockIdx.x * FDIM + tid] = s_tot[tid];
    }
    if (tid < 2) g_psq[blockIdx.x * 2 + tid] = s_sq[tid];
}

// ---------------------------------------------------------------------------
// Kernel 2: one warp per (b,c). Combine chunk partials, compute opS/opQ
// scalars, softmax weights, BN partial sums.
// ---------------------------------------------------------------------------
__global__ __launch_bounds__(256) void k2(const float* __restrict__ h,
                                          const float* __restrict__ opS,
                                          const float* __restrict__ opQ) {
    const int bc   = blockIdx.x * 8 + (threadIdx.x >> 5);
    const int c    = bc & (CDIM - 1);
    const int lane = threadIdx.x & 31;

    const float4* ps = (const float4*)(g_psupp + (size_t)bc * 2 * FDIM);
    const float4* pt = (const float4*)(g_ptot  + (size_t)bc * 2 * FDIM);
    float4 sa = ps[lane], sb = ps[lane + 32];
    float4 ta = pt[lane], tb = pt[lane + 32];
    float4 sp = make_float4(sa.x + sb.x, sa.y + sb.y, sa.z + sb.z, sa.w + sb.w);
    float4 tt = make_float4(ta.x + tb.x, ta.y + tb.y, ta.z + tb.z, ta.w + tb.w);

    const float4 src = ((const float4*)(h + (size_t)bc * NDIM * FDIM))[lane];
    const float4 oS0 = ((const float4*)(opS + c * 2 * FDIM))[lane];
    const float4 oS1 = ((const float4*)(opS + c * 2 * FDIM + FDIM))[lane];
    const float4 oQ0 = ((const float4*)(opQ + c * 2 * FDIM))[lane];
    const float4 oQ1 = ((const float4*)(opQ + c * 2 * FDIM + FDIM))[lane];

    const float invN = 1.f / (float)NDIM;
    float4 qm = make_float4(tt.x - sp.x, tt.y - sp.y, tt.z - sp.z, tt.w - sp.w);

    float tS = (sp.x * oS0.x + sp.y * oS0.y + sp.z * oS0.z + sp.w * oS0.w) * invN
             + (src.x * oS1.x + src.y * oS1.y + src.z * oS1.z + src.w * oS1.w);
    float tQ = (qm.x * oQ0.x + qm.y * oQ0.y + qm.z * oQ0.z + qm.w * oQ0.w) * invN
             + (src.x * oQ1.x + src.y * oQ1.y + src.z * oQ1.z + src.w * oQ1.w);
    float sumS = sp.x + sp.y + sp.z + sp.w;
    float sumT = tt.x + tt.y + tt.z + tt.w;

    tS = warpsum(tS);
    tQ = warpsum(tQ);
    sumS = warpsum(sumS);
    sumT = warpsum(sumT);

    if (lane == 0) {
        const float mx = fmaxf(tS, tQ);
        const float e0 = expf(tS - mx), e1 = expf(tQ - mx);
        const float inv = 1.f / (e0 + e1);
        const float w0 = e0 * inv, w1 = e1 * inv;
        g_w[bc] = make_float2(w0, w1);
        const float sqS = g_psq[bc * 4 + 0] + g_psq[bc * 4 + 2];
        const float sqT = g_psq[bc * 4 + 1] + g_psq[bc * 4 + 3];
        g_S1[bc] = w0 * sumS + w1 * (sumT - sumS);
        g_S2[bc] = w0 * w0 * sqS + w1 * w1 * (sqT - sqS);
    }
}

// ---------------------------------------------------------------------------
// Kernel 2b: fold batch partials -> per-channel (mean, rstd). One tiny block.
// ---------------------------------------------------------------------------
__global__ void k2b() {
    const int c = threadIdx.x;
    float s1 = 0.f, s2 = 0.f;
#pragma unroll
    for (int b = 0; b < BDIM; b++) {
        s1 += g_S1[b * CDIM + c];
        s2 += g_S2[b * CDIM + c];
    }
    const float inv = 1.f / (float)(BDIM * NDIM * FDIM);
    const float mean = s1 * inv;
    const float var = s2 * inv - mean * mean;
    g_stat[c] = make_float2(mean, rsqrtf(var + EPS));
}

// ---------------------------------------------------------------------------
// Kernel 3: streaming elementwise: elu((h*w - mean)*rstd*gamma + beta)
// ---------------------------------------------------------------------------
__global__ __launch_bounds__(256) void k3(const float* __restrict__ h,
                                          const float* __restrict__ gamma,
                                          const float* __restrict__ beta,
                                          float* __restrict__ out) {
    const int i = blockIdx.x * blockDim.x + threadIdx.x;  // float4 index
    const int e = i << 2;                                 // element index
    const int n = (e >> 7) & (NDIM - 1);
    const int bc = e >> 15;                               // 256*128 = 2^15
    const int c = bc & (CDIM - 1);

    const unsigned char m = g_mask[(bc << 8) + n];
    const float2 wv = g_w[bc];
    const float w = m ? wv.x : wv.y;
    const float2 st = g_stat[c];
    const float gr = gamma[c] * st.y;
    const float scale = w * gr;
    const float shift = beta[c] - st.x * gr;

    const float4 hv = ((const float4*)h)[i];
    float4 y;
    y.x = hv.x * scale + shift;
    y.y = hv.y * scale + shift;
    y.z = hv.z * scale + shift;
    y.w = hv.w * scale + shift;
    y.x = (y.x > 0.f) ? y.x : (__expf(y.x) - 1.f);
    y.y = (y.y > 0.f) ? y.y : (__expf(y.y) - 1.f);
    y.z = (y.z > 0.f) ? y.z : (__expf(y.z) - 1.f);
    y.w = (y.w > 0.f) ? y.w : (__expf(y.w) - 1.f);
    __stcs(&((float4*)out)[i], y);
}

extern "C" void kernel_launch(void* const* d_in, const int* in_sizes, int n_in,
                              void* d_out, int out_size) {
    const float* h     = (const float*)d_in[0];
    const float* op    = (const float*)d_in[1];
    const float* opS   = (const float*)d_in[2];
    const float* opQ   = (const float*)d_in[3];
    const float* gamma = (const float*)d_in[4];
    const float* beta  = (const float*)d_in[5];
    float* out = (float*)d_out;

    k1<<<BDIM * CDIM * 2, 256>>>(h, op);
    k2<<<BDIM * CDIM / 8, 256>>>(h, opS, opQ);
    k2b<<<1, CDIM>>>();
    const int total4 = (BDIM * CDIM * NDIM * FDIM) / 4;  // 4,194,304
    k3<<<total4 / 256, 256>>>(h, gamma, beta, out);
}